// round 4
// baseline (speedup 1.0000x reference)
#include <cuda_runtime.h>
#include <cuda_bf16.h>
#include <math.h>

// Problem constants
#define B_  32
#define N_  4096
#define C_  512
#define EPS_INV 10.0f          // 1/EPS_SINKHORN

#define CHUNKS 32              // chunk-blocks per batch
#define ROWS_PER_BLOCK (N_ / CHUNKS)   // 128
#define THREADS1 256           // 8 warps
#define NWARPS (THREADS1 / 32)

// Scratch (allocation-free rule: __device__ globals)
__device__ float        g_vec[B_ * CHUNKS * C_];   // partial weighted sums: 2 MB
__device__ float        g_E[B_ * CHUNKS];          // partial exp-sums
__device__ unsigned int g_cnt[B_];                 // zero-init; last block resets -> replayable

// ---------------------------------------------------------------------------
// Single fused kernel: stream visual_feats once; the last chunk-block of each
// batch performs the cross-chunk combine + dustbin + output write.
//
// Per row: w_raw = exp(10*(cos_sim - 1)) (shift m=0 valid since cos_sim <= 1),
// accumulate w_raw/|v| * v  and  w_raw.  Softmax Z folds out analytically:
//   obs = num / (E + 1e-6*S),  total_mass = E / S,  S = E + exp(-10*dustbin).
// ---------------------------------------------------------------------------
__global__ __launch_bounds__(THREADS1)
void uot_fused(const float* __restrict__ prompt,
               const float* __restrict__ vfeats,
               const float* __restrict__ dustbin_param,
               float* __restrict__ out)
{
    const int b     = blockIdx.x / CHUNKS;
    const int chunk = blockIdx.x % CHUNKS;
    const int tid   = threadIdx.x;
    const int wid   = tid >> 5;
    const int lane  = tid & 31;

    __shared__ float sp[C_];                 // raw prompt row
    __shared__ float sacc[NWARPS][C_];       // per-warp partial vector sums
    __shared__ float sEw[NWARPS];
    __shared__ float s_pinv;                 // 1/|p|
    __shared__ int   s_last;

    // ---- Load prompt row + compute its norm ----
    float ss = 0.f;
    #pragma unroll
    for (int i = tid; i < C_; i += THREADS1) {
        float v = prompt[b * C_ + i];
        sp[i] = v;
        ss += v * v;
    }
    #pragma unroll
    for (int o = 16; o; o >>= 1) ss += __shfl_xor_sync(0xffffffffu, ss, o);
    if (lane == 0) sEw[wid] = ss;            // temp reuse
    __syncthreads();
    if (tid == 0) {
        float t = 0.f;
        #pragma unroll
        for (int w = 0; w < NWARPS; w++) t += sEw[w];
        s_pinv = rsqrtf(fmaxf(t, 1e-24f));
    }
    __syncthreads();
    const float pinv = s_pinv;

    // ---- Main streaming loop: 2 rows per warp per iteration (MLP x2) ----
    float acc[16];
    #pragma unroll
    for (int i = 0; i < 16; i++) acc[i] = 0.f;
    float Eacc = 0.f;

    const float4* pr4 = (const float4*)sp;
    const float* base = vfeats + ((size_t)b * N_ + (size_t)chunk * ROWS_PER_BLOCK) * C_;

    #pragma unroll 2
    for (int r = wid; r < ROWS_PER_BLOCK; r += 2 * NWARPS) {
        const float4* rowA = (const float4*)(base + (size_t)r * C_);
        const float4* rowB = (const float4*)(base + (size_t)(r + NWARPS) * C_);
        float4 va[4], vb[4];
        float dpa = 0.f, dva = 0.f, dpb = 0.f, dvb = 0.f;
        #pragma unroll
        for (int j = 0; j < 4; j++) {
            va[j] = __ldcs(rowA + j * 32 + lane);
            vb[j] = __ldcs(rowB + j * 32 + lane);
        }
        #pragma unroll
        for (int j = 0; j < 4; j++) {
            float4 p4 = pr4[j * 32 + lane];
            dpa += va[j].x * p4.x + va[j].y * p4.y + va[j].z * p4.z + va[j].w * p4.w;
            dva += va[j].x * va[j].x + va[j].y * va[j].y + va[j].z * va[j].z + va[j].w * va[j].w;
            dpb += vb[j].x * p4.x + vb[j].y * p4.y + vb[j].z * p4.z + vb[j].w * p4.w;
            dvb += vb[j].x * vb[j].x + vb[j].y * vb[j].y + vb[j].z * vb[j].z + vb[j].w * vb[j].w;
        }
        #pragma unroll
        for (int o = 16; o; o >>= 1) {
            dpa += __shfl_xor_sync(0xffffffffu, dpa, o);
            dva += __shfl_xor_sync(0xffffffffu, dva, o);
            dpb += __shfl_xor_sync(0xffffffffu, dpb, o);
            dvb += __shfl_xor_sync(0xffffffffu, dvb, o);
        }
        float invnA = rsqrtf(fmaxf(dva, 1e-24f));
        float invnB = rsqrtf(fmaxf(dvb, 1e-24f));
        float eA    = __expf(EPS_INV * (dpa * invnA * pinv - 1.0f));
        float eB    = __expf(EPS_INV * (dpb * invnB * pinv - 1.0f));
        float wA    = eA * invnA;            // weight applied to the RAW row
        float wB    = eB * invnB;
        Eacc += eA + eB;
        #pragma unroll
        for (int j = 0; j < 4; j++) {
            acc[j * 4 + 0] += wA * va[j].x + wB * vb[j].x;
            acc[j * 4 + 1] += wA * va[j].y + wB * vb[j].y;
            acc[j * 4 + 2] += wA * va[j].z + wB * vb[j].z;
            acc[j * 4 + 3] += wA * va[j].w + wB * vb[j].w;
        }
    }

    // ---- Cross-warp combine in smem ----
    float4* sa4 = (float4*)sacc[wid];
    #pragma unroll
    for (int j = 0; j < 4; j++)
        sa4[j * 32 + lane] = make_float4(acc[j*4+0], acc[j*4+1], acc[j*4+2], acc[j*4+3]);
    __syncthreads();
    if (lane == 0) sEw[wid] = Eacc;          // all reads of old sEw done pre-sync
    __syncthreads();

    const int slot = b * CHUNKS + chunk;
    #pragma unroll
    for (int c = tid; c < C_; c += THREADS1) {
        float s = 0.f;
        #pragma unroll
        for (int w = 0; w < NWARPS; w++) s += sacc[w][c];
        g_vec[slot * C_ + c] = s;
    }
    if (tid == 0) {
        float s = 0.f;
        #pragma unroll
        for (int w = 0; w < NWARPS; w++) s += sEw[w];
        g_E[slot] = s;
    }

    // ---- Last-block-per-batch does the final combine (replaces pass 2) ----
    __syncthreads();                          // all partial stores issued
    if (tid == 0) {
        __threadfence();                      // release partials
        unsigned int old = atomicAdd(&g_cnt[b], 1u);
        s_last = (old == CHUNKS - 1);
    }
    __syncthreads();
    if (!s_last) return;
    __threadfence();                          // acquire others' partials

    // Reduce the 32 per-chunk exp-sums (warp 0)
    __shared__ float s_Etot;
    if (tid < 32) {
        float e = g_E[b * CHUNKS + tid];      // CHUNKS == 32
        #pragma unroll
        for (int o = 16; o; o >>= 1) e += __shfl_xor_sync(0xffffffffu, e, o);
        if (tid == 0) s_Etot = e;
    }
    __syncthreads();

    const float E    = s_Etot;
    const float ebin = __expf(-EPS_INV * dustbin_param[0]);
    const float S    = E + ebin;
    const float dinv = 1.0f / (E + 1e-6f * S);

    #pragma unroll
    for (int c = tid; c < C_; c += THREADS1) {
        float num = 0.f;
        #pragma unroll
        for (int ch = 0; ch < CHUNKS; ch++)
            num += g_vec[(b * CHUNKS + ch) * C_ + c];
        out[b * C_ + c] = num * dinv;
    }
    if (tid == 0) {
        out[B_ * C_ + b] = E / S;             // total_mass
        g_cnt[b] = 0;                         // reset for next graph replay
    }
}

// ---------------------------------------------------------------------------
extern "C" void kernel_launch(void* const* d_in, const int* in_sizes, int n_in,
                              void* d_out, int out_size)
{
    const float* prompt  = (const float*)d_in[0];   // (32,1,512)
    const float* vfeats  = (const float*)d_in[1];   // (32,4096,512)
    // d_in[2] = dustbin_token : unused by the reference computation
    const float* dparam  = (const float*)d_in[3];   // (1,)
    float* out = (float*)d_out;

    uot_fused<<<B_ * CHUNKS, THREADS1>>>(prompt, vfeats, dparam, out);
}

// round 5
// speedup vs baseline: 1.3293x; 1.3293x over previous
#include <cuda_runtime.h>
#include <cuda_bf16.h>
#include <math.h>

// Problem constants
#define B_  32
#define N_  4096
#define C_  512
#define EPS_INV 10.0f          // 1/EPS_SINKHORN

#define CHUNKS 32              // chunk-blocks per batch
#define ROWS_PER_BLOCK (N_ / CHUNKS)   // 128
#define THREADS1 256           // 8 warps
#define NWARPS (THREADS1 / 32)

// Scratch (allocation-free rule: __device__ globals)
__device__ float        g_vec[B_ * CHUNKS * C_];   // partial weighted sums: 2 MB
__device__ float        g_E[B_ * CHUNKS];          // partial exp-sums
__device__ unsigned int g_cnt[B_];                 // zero-init; last block resets -> replayable

// ---------------------------------------------------------------------------
// Single fused kernel: stream visual_feats once (1 row per warp per iter to
// keep regs <= 64 and occupancy at 4 blocks/SM); last chunk-block of each
// batch performs the cross-chunk combine + dustbin + output write.
//
// Per row: e = exp(10*(cos_sim - 1)) (shift m=0 valid since cos_sim <= 1),
// accumulate (e/|v|)*v and e. Softmax Z folds out analytically:
//   obs = num / (E + 1e-6*S),  total_mass = E / S,  S = E + exp(-10*dustbin).
// ---------------------------------------------------------------------------
__global__ __launch_bounds__(THREADS1, 4)
void uot_fused(const float* __restrict__ prompt,
               const float* __restrict__ vfeats,
               const float* __restrict__ dustbin_param,
               float* __restrict__ out)
{
    const int b     = blockIdx.x / CHUNKS;
    const int chunk = blockIdx.x % CHUNKS;
    const int tid   = threadIdx.x;
    const int wid   = tid >> 5;
    const int lane  = tid & 31;

    __shared__ float sp[C_];                 // raw prompt row
    __shared__ float sacc[NWARPS][C_];       // per-warp partial vector sums
    __shared__ float sEw[NWARPS];
    __shared__ float s_pinv;                 // 1/|p|
    __shared__ int   s_last;

    // ---- Load prompt row + compute its norm ----
    float ss = 0.f;
    #pragma unroll
    for (int i = tid; i < C_; i += THREADS1) {
        float v = prompt[b * C_ + i];
        sp[i] = v;
        ss += v * v;
    }
    #pragma unroll
    for (int o = 16; o; o >>= 1) ss += __shfl_xor_sync(0xffffffffu, ss, o);
    if (lane == 0) sEw[wid] = ss;            // temp reuse
    __syncthreads();
    if (tid == 0) {
        float t = 0.f;
        #pragma unroll
        for (int w = 0; w < NWARPS; w++) t += sEw[w];
        s_pinv = rsqrtf(fmaxf(t, 1e-24f));
    }
    __syncthreads();
    const float pinv = s_pinv;

    // ---- Main streaming loop: 1 row per warp per iteration ----
    float acc[16];
    #pragma unroll
    for (int i = 0; i < 16; i++) acc[i] = 0.f;
    float Eacc = 0.f;

    const float4* pr4 = (const float4*)sp;
    const float* base = vfeats + ((size_t)b * N_ + (size_t)chunk * ROWS_PER_BLOCK) * C_;

    for (int r = wid; r < ROWS_PER_BLOCK; r += NWARPS) {
        const float4* row = (const float4*)(base + (size_t)r * C_);
        float4 v[4];
        float dpv = 0.f, dvv = 0.f;
        #pragma unroll
        for (int j = 0; j < 4; j++)
            v[j] = __ldcs(row + j * 32 + lane);
        #pragma unroll
        for (int j = 0; j < 4; j++) {
            float4 p4 = pr4[j * 32 + lane];
            dpv += v[j].x * p4.x + v[j].y * p4.y + v[j].z * p4.z + v[j].w * p4.w;
            dvv += v[j].x * v[j].x + v[j].y * v[j].y + v[j].z * v[j].z + v[j].w * v[j].w;
        }
        #pragma unroll
        for (int o = 16; o; o >>= 1) {
            dpv += __shfl_xor_sync(0xffffffffu, dpv, o);
            dvv += __shfl_xor_sync(0xffffffffu, dvv, o);
        }
        float invn = rsqrtf(fmaxf(dvv, 1e-24f));
        float e    = __expf(EPS_INV * (dpv * invn * pinv - 1.0f));
        float w    = e * invn;               // weight applied to the RAW row
        Eacc += e;
        #pragma unroll
        for (int j = 0; j < 4; j++) {
            acc[j * 4 + 0] += w * v[j].x;
            acc[j * 4 + 1] += w * v[j].y;
            acc[j * 4 + 2] += w * v[j].z;
            acc[j * 4 + 3] += w * v[j].w;
        }
    }

    // ---- Cross-warp combine in smem ----
    float4* sa4 = (float4*)sacc[wid];
    #pragma unroll
    for (int j = 0; j < 4; j++)
        sa4[j * 32 + lane] = make_float4(acc[j*4+0], acc[j*4+1], acc[j*4+2], acc[j*4+3]);
    __syncthreads();
    if (lane == 0) sEw[wid] = Eacc;          // all reads of old sEw done pre-sync
    __syncthreads();

    const int slot = b * CHUNKS + chunk;
    #pragma unroll
    for (int c = tid; c < C_; c += THREADS1) {
        float s = 0.f;
        #pragma unroll
        for (int w = 0; w < NWARPS; w++) s += sacc[w][c];
        g_vec[slot * C_ + c] = s;
    }
    if (tid == 0) {
        float s = 0.f;
        #pragma unroll
        for (int w = 0; w < NWARPS; w++) s += sEw[w];
        g_E[slot] = s;
    }

    // ---- Last-block-per-batch does the final combine (replaces pass 2) ----
    __syncthreads();                          // all partial stores issued
    if (tid == 0) {
        __threadfence();                      // release partials
        unsigned int old = atomicAdd(&g_cnt[b], 1u);
        s_last = (old == CHUNKS - 1);
    }
    __syncthreads();
    if (!s_last) return;
    __threadfence();                          // acquire others' partials

    // Reduce the 32 per-chunk exp-sums (warp 0)
    __shared__ float s_Etot;
    if (tid < 32) {
        float e = g_E[b * CHUNKS + tid];      // CHUNKS == 32
        #pragma unroll
        for (int o = 16; o; o >>= 1) e += __shfl_xor_sync(0xffffffffu, e, o);
        if (tid == 0) s_Etot = e;
    }
    __syncthreads();

    const float E    = s_Etot;
    const float ebin = __expf(-EPS_INV * dustbin_param[0]);
    const float S    = E + ebin;
    const float dinv = 1.0f / (E + 1e-6f * S);

    #pragma unroll
    for (int c = tid; c < C_; c += THREADS1) {
        float num = 0.f;
        #pragma unroll
        for (int ch = 0; ch < CHUNKS; ch++)
            num += g_vec[(b * CHUNKS + ch) * C_ + c];
        out[b * C_ + c] = num * dinv;
    }
    if (tid == 0) {
        out[B_ * C_ + b] = E / S;             // total_mass
        g_cnt[b] = 0;                         // reset for next graph replay
    }
}

// ---------------------------------------------------------------------------
extern "C" void kernel_launch(void* const* d_in, const int* in_sizes, int n_in,
                              void* d_out, int out_size)
{
    const float* prompt  = (const float*)d_in[0];   // (32,1,512)
    const float* vfeats  = (const float*)d_in[1];   // (32,4096,512)
    // d_in[2] = dustbin_token : unused by the reference computation
    const float* dparam  = (const float*)d_in[3];   // (1,)
    float* out = (float*)d_out;

    uot_fused<<<B_ * CHUNKS, THREADS1>>>(prompt, vfeats, dparam, out);
}

// round 7
// speedup vs baseline: 1.3546x; 1.0190x over previous
#include <cuda_runtime.h>
#include <cuda_bf16.h>
#include <math.h>

// Problem constants
#define B_  32
#define N_  4096
#define C_  512
#define EPS_INV 10.0f          // 1/EPS_SINKHORN

#define CHUNKS 16              // chunk-blocks per batch -> grid 512 = ONE resident wave
#define ROWS_PER_BLOCK (N_ / CHUNKS)   // 256
#define THREADS1 256           // 8 warps
#define NWARPS (THREADS1 / 32)

// Scratch (allocation-free rule: __device__ globals)
__device__ float        g_vec[B_ * CHUNKS * C_];   // partial weighted sums: 1 MB
__device__ float        g_E[B_ * CHUNKS];          // partial exp-sums
__device__ unsigned int g_cnt[B_];                 // zero-init; last block resets -> replayable

// ---------------------------------------------------------------------------
// Fused single-pass kernel, software-pipelined: each warp prefetches the next
// row's 4x LDG.128 before running the current row's reduce/exp chain, so DRAM
// latency hides under the shfl/MUFU chain. Last chunk-block per batch combines.
//
// Per row: e = exp(10*(cos_sim - 1)) (shift m=0 valid since cos_sim <= 1),
// accumulate (e/|v|)*v and e. Softmax Z folds out analytically:
//   obs = num / (E + 1e-6*S),  total_mass = E / S,  S = E + exp(-10*dustbin).
// ---------------------------------------------------------------------------
__global__ __launch_bounds__(THREADS1, 4)
void uot_fused(const float* __restrict__ prompt,
               const float* __restrict__ vfeats,
               const float* __restrict__ dustbin_param,
               float* __restrict__ out)
{
    const int b     = blockIdx.x / CHUNKS;
    const int chunk = blockIdx.x % CHUNKS;
    const int tid   = threadIdx.x;
    const int wid   = tid >> 5;
    const int lane  = tid & 31;

    __shared__ float sp[C_];                 // raw prompt row
    __shared__ float sacc[NWARPS][C_];       // per-warp partial vector sums
    __shared__ float sEw[NWARPS];
    __shared__ float s_pinv;                 // 1/|p|
    __shared__ int   s_last;

    // ---- Load prompt row + compute its norm ----
    float ss = 0.f;
    #pragma unroll
    for (int i = tid; i < C_; i += THREADS1) {
        float v = prompt[b * C_ + i];
        sp[i] = v;
        ss += v * v;
    }
    #pragma unroll
    for (int o = 16; o; o >>= 1) ss += __shfl_xor_sync(0xffffffffu, ss, o);
    if (lane == 0) sEw[wid] = ss;            // temp reuse
    __syncthreads();
    if (tid == 0) {
        float t = 0.f;
        #pragma unroll
        for (int w = 0; w < NWARPS; w++) t += sEw[w];
        s_pinv = rsqrtf(fmaxf(t, 1e-24f));
    }
    __syncthreads();
    const float pinv = s_pinv;

    // ---- Main streaming loop: pipelined, 1 row per warp per iteration ----
    float acc[16];
    #pragma unroll
    for (int i = 0; i < 16; i++) acc[i] = 0.f;
    float Eacc = 0.f;

    const float4* pr4 = (const float4*)sp;
    const float* base = vfeats + ((size_t)b * N_ + (size_t)chunk * ROWS_PER_BLOCK) * C_;

    // Prologue: prefetch this warp's first row
    float4 v[4];
    {
        const float4* row0 = (const float4*)(base + (size_t)wid * C_);
        #pragma unroll
        for (int j = 0; j < 4; j++) v[j] = __ldcs(row0 + j * 32 + lane);
    }

    for (int r = wid; r < ROWS_PER_BLOCK; r += NWARPS) {
        // Snapshot current row, immediately issue next row's loads
        float4 c[4];
        #pragma unroll
        for (int j = 0; j < 4; j++) c[j] = v[j];

        const int rn = r + NWARPS;
        if (rn < ROWS_PER_BLOCK) {
            const float4* rown = (const float4*)(base + (size_t)rn * C_);
            #pragma unroll
            for (int j = 0; j < 4; j++) v[j] = __ldcs(rown + j * 32 + lane);
        }

        // Dot products on current row (overlaps next row's DRAM latency)
        float dpv = 0.f, dvv = 0.f;
        #pragma unroll
        for (int j = 0; j < 4; j++) {
            float4 p4 = pr4[j * 32 + lane];
            dpv += c[j].x * p4.x + c[j].y * p4.y + c[j].z * p4.z + c[j].w * p4.w;
            dvv += c[j].x * c[j].x + c[j].y * c[j].y + c[j].z * c[j].z + c[j].w * c[j].w;
        }
        #pragma unroll
        for (int o = 16; o; o >>= 1) {
            dpv += __shfl_xor_sync(0xffffffffu, dpv, o);
            dvv += __shfl_xor_sync(0xffffffffu, dvv, o);
        }
        float invn = rsqrtf(fmaxf(dvv, 1e-24f));
        float e    = __expf(EPS_INV * (dpv * invn * pinv - 1.0f));
        float w    = e * invn;               // weight applied to the RAW row
        Eacc += e;
        #pragma unroll
        for (int j = 0; j < 4; j++) {
            acc[j * 4 + 0] += w * c[j].x;
            acc[j * 4 + 1] += w * c[j].y;
            acc[j * 4 + 2] += w * c[j].z;
            acc[j * 4 + 3] += w * c[j].w;
        }
    }

    // ---- Cross-warp combine in smem ----
    float4* sa4 = (float4*)sacc[wid];
    #pragma unroll
    for (int j = 0; j < 4; j++)
        sa4[j * 32 + lane] = make_float4(acc[j*4+0], acc[j*4+1], acc[j*4+2], acc[j*4+3]);
    __syncthreads();
    if (lane == 0) sEw[wid] = Eacc;          // all reads of old sEw done pre-sync
    __syncthreads();

    const int slot = b * CHUNKS + chunk;
    #pragma unroll
    for (int c = tid; c < C_; c += THREADS1) {
        float s = 0.f;
        #pragma unroll
        for (int w = 0; w < NWARPS; w++) s += sacc[w][c];
        g_vec[slot * C_ + c] = s;
    }
    if (tid == 0) {
        float s = 0.f;
        #pragma unroll
        for (int w = 0; w < NWARPS; w++) s += sEw[w];
        g_E[slot] = s;
    }

    // ---- Last-block-per-batch does the final combine ----
    __syncthreads();                          // all partial stores issued
    if (tid == 0) {
        __threadfence();                      // release partials
        unsigned int old = atomicAdd(&g_cnt[b], 1u);
        s_last = (old == CHUNKS - 1);
    }
    __syncthreads();
    if (!s_last) return;
    __threadfence();                          // acquire others' partials

    // Reduce the CHUNKS(=16) per-chunk exp-sums (lanes 0..15 of warp 0)
    __shared__ float s_Etot;
    if (tid < CHUNKS) {
        float e = g_E[b * CHUNKS + tid];
        #pragma unroll
        for (int o = CHUNKS / 2; o; o >>= 1)
            e += __shfl_xor_sync(0x0000ffffu, e, o);
        if (tid == 0) s_Etot = e;
    }
    __syncthreads();

    const float E    = s_Etot;
    const float ebin = __expf(-EPS_INV * dustbin_param[0]);
    const float S    = E + ebin;
    const float dinv = 1.0f / (E + 1e-6f * S);

    #pragma unroll
    for (int c = tid; c < C_; c += THREADS1) {
        float num = 0.f;
        #pragma unroll
        for (int ch = 0; ch < CHUNKS; ch++)
            num += g_vec[(b * CHUNKS + ch) * C_ + c];
        out[b * C_ + c] = num * dinv;
    }
    if (tid == 0) {
        out[B_ * C_ + b] = E / S;             // total_mass
        g_cnt[b] = 0;                         // reset for next graph replay
    }
}

// ---------------------------------------------------------------------------
extern "C" void kernel_launch(void* const* d_in, const int* in_sizes, int n_in,
                              void* d_out, int out_size)
{
    const float* prompt  = (const float*)d_in[0];   // (32,1,512)
    const float* vfeats  = (const float*)d_in[1];   // (32,4096,512)
    // d_in[2] = dustbin_token : unused by the reference computation
    const float* dparam  = (const float*)d_in[3];   // (1,)
    float* out = (float*)d_out;

    uot_fused<<<B_ * CHUNKS, THREADS1>>>(prompt, vfeats, dparam, out);
}